// round 7
// baseline (speedup 1.0000x reference)
#include <cuda_runtime.h>
#include <cuda_bf16.h>
#include <cstdint>

#define BSZ    256
#define FEAT   128
#define KP1    4097
#define PAD    4100
#define NDATA  500000
#define SDIM   1024
#define TDIM   2048
#define MEMELEMS 64000000
#define TOTAL  (BSZ * KP1)        // 1,048,832
#define EPSF   1e-7f
#define MPN    (4096.0f / 500000.0f)
#define N4     15999999
#define KSPLIT 8
#define FULLM  0xffffffffu
#define CAP    16
#define LOSS_BLOCKS 1280
#define NCE_CTAS 148
#define NCE_THR  1024
#define NWARPS   (NCE_CTAS * 32)   // 4736
#define CHUNK    106               // 4736*106 = 502,016 >= NDATA

__device__ float g_es[BSZ * FEAT];
__device__ float g_et[BSZ * FEAT];
__device__ float g_part_s[KSPLIT * BSZ * FEAT];
__device__ float g_part_t[KSPLIT * BSZ * FEAT];
__device__ float g_out_s[BSZ * PAD];
__device__ float g_out_t[BSZ * PAD];
__device__ float g_sums[3];
__device__ int   g_ticket;
__device__ int   g_cnt[NDATA];
__device__ int   g_tasklist[NDATA * CAP];   // global task id i = b*KP1+k

// ---------------------------------------------------------------- embed partial (split-K) + cnt zeroing
__global__ __launch_bounds__(128) void embed_partial(const float* __restrict__ f_s,
                                                     const float* __restrict__ f_t,
                                                     const float* __restrict__ W_s,
                                                     const float* __restrict__ W_t) {
    {
        const int tid = blockIdx.x * 128 + threadIdx.x;   // 131072 threads
        for (int z = tid; z < NDATA; z += 1024 * 128) g_cnt[z] = 0;
        if (tid == 0) { g_sums[0] = 0.f; g_sums[1] = 0.f; g_sums[2] = 0.f; g_ticket = 0; }
    }
    __shared__ float fsh[4 * 256];
    const int bid = blockIdx.x;
    const bool is_t = bid >= 512;
    const int id = is_t ? bid - 512 : bid;
    const int rt = id >> 3;
    const int ks = id & 7;
    const int Kd = is_t ? TDIM : SDIM;
    const int kchunk = Kd / KSPLIT;
    const int k0 = ks * kchunk;
    const float* f = is_t ? f_t : f_s;
    const float* W = is_t ? W_t : W_s;
    float* part = is_t ? g_part_t : g_part_s;
    const int rows0 = rt * 4;
    const int t = threadIdx.x;

    #pragma unroll
    for (int r = 0; r < 4; ++r)
        for (int k = t; k < kchunk; k += 128)
            fsh[r * 256 + k] = f[(rows0 + r) * Kd + k0 + k];
    __syncthreads();

    float a0 = 0.f, a1 = 0.f, a2 = 0.f, a3 = 0.f;
    const float* Wp = W + (size_t)k0 * FEAT + t;
    #pragma unroll 8
    for (int k = 0; k < kchunk; ++k) {
        float w = Wp[(size_t)k * FEAT];
        a0 += fsh[k] * w;
        a1 += fsh[256 + k] * w;
        a2 += fsh[512 + k] * w;
        a3 += fsh[768 + k] * w;
    }
    part[(ks * BSZ + rows0 + 0) * FEAT + t] = a0;
    part[(ks * BSZ + rows0 + 1) * FEAT + t] = a1;
    part[(ks * BSZ + rows0 + 2) * FEAT + t] = a2;
    part[(ks * BSZ + rows0 + 3) * FEAT + t] = a3;
}

// ---------------------------------------------------------------- normalize + exact-row scatter
// bid<512: normalize row. bid>=512 (1024 blocks): scatter tasks into per-row bins.
__global__ __launch_bounds__(128) void norm_scatter(const float* __restrict__ b_s,
                                                    const float* __restrict__ b_t,
                                                    const int* __restrict__ cidx) {
    const int bid = blockIdx.x;
    const int t = threadIdx.x;
    if (bid < 512) {
        const bool is_t = bid >= 256;
        const int row = is_t ? bid - 256 : bid;
        const float* part = is_t ? g_part_t : g_part_s;
        const float* bias = is_t ? b_t : b_s;
        float* out = is_t ? g_et : g_es;

        float v = bias[t];
        #pragma unroll
        for (int ks = 0; ks < KSPLIT; ++ks)
            v += part[(ks * BSZ + row) * FEAT + t];

        float sq = v * v;
        #pragma unroll
        for (int o = 16; o; o >>= 1) sq += __shfl_xor_sync(FULLM, sq, o);
        __shared__ float sh[4];
        const int lane = t & 31, w_ = t >> 5;
        if (lane == 0) sh[w_] = sq;
        __syncthreads();
        float tot = sh[0] + sh[1] + sh[2] + sh[3];
        out[row * FEAT + t] = v / sqrtf(tot);
        return;
    }
    const int tid = (bid - 512) * 128 + t;
    #pragma unroll 1
    for (int i = tid; i < TOTAL; i += 1024 * 128) {
        const int row = __ldg(cidx + i);
        const int pos = atomicAdd(&g_cnt[row], 1);
        if (pos < CAP)
            g_tasklist[(size_t)row * CAP + pos] = i;
    }
}

// ---------------------------------------------------------------- NCE: dedup gather, smem bf16 embeddings
// 148 persistent CTAs x 1024 thr, 1/SM. Dynamic smem: es(64K) + et(64K) + lists(16K).
__global__ __launch_bounds__(NCE_THR, 1) void nce_kernel(const float* __restrict__ m1,
                                                         const float* __restrict__ m2) {
    extern __shared__ char sm[];
    __nv_bfloat16* esb = (__nv_bfloat16*)sm;              // 64 KB
    __nv_bfloat16* etb = (__nv_bfloat16*)(sm + 65536);    // 64 KB
    int* lists = (int*)(sm + 131072);                     // 32 warps * 128 ints
    __shared__ float shT[32], shS[32];

    const int t = threadIdx.x;
    // stage embeddings to smem as bf16
    for (int i = t; i < BSZ * FEAT; i += NCE_THR) {
        esb[i] = __float2bfloat16(g_es[i]);
        etb[i] = __float2bfloat16(g_et[i]);
    }
    __syncthreads();

    const int lane = t & 31;
    const int w = t >> 5;
    const int gw = blockIdx.x * 32 + w;     // 0..4735
    const int r0 = gw * CHUNK;
    int* mylist = lists + w * 128;

    // compaction: list of (row<<5)|cnt for nonzero rows in this warp's chunk
    int nlist = 0;
    #pragma unroll 1
    for (int base = 0; base < CHUNK; base += 32) {
        const int r = r0 + base + lane;
        int c = 0;
        if (base + lane < CHUNK && r < NDATA) c = __ldg(&g_cnt[r]);
        if (c > CAP) c = CAP;
        const unsigned bal = __ballot_sync(FULLM, c > 0);
        if (c > 0) {
            const int pos = nlist + __popc(bal & ((1u << lane) - 1));
            mylist[pos] = (r << 5) | c;
        }
        nlist += __popc(bal);
    }
    __syncwarp();

    float sumT = 0.f, sumS = 0.f;

    #pragma unroll 1
    for (int i0 = 0; i0 < nlist; i0 += 4) {
        const int m = min(4, nlist - i0);
        int rows[4], cs[4];
        #pragma unroll
        for (int j = 0; j < 4; ++j) {
            const int e = mylist[i0 + ((j < m) ? j : m - 1)];
            rows[j] = e >> 5; cs[j] = e & 31;
        }
        float4 A[4], C[4];
        #pragma unroll
        for (int j = 0; j < 4; ++j) {
            A[j] = __ldg((const float4*)m1 + (size_t)rows[j] * 32 + lane);
            C[j] = __ldg((const float4*)m2 + (size_t)rows[j] * 32 + lane);
        }
        #pragma unroll 1
        for (int j = 0; j < m; ++j) {
            int rec = 0;
            if (lane < cs[j]) rec = __ldg(&g_tasklist[(size_t)rows[j] * CAP + lane]);
            #pragma unroll 1
            for (int tt = 0; tt < cs[j]; ++tt) {
                const int i = __shfl_sync(FULLM, rec, tt);
                const int b = i / KP1;
                const int k = i - b * KP1;
                const __nv_bfloat162* ept = (const __nv_bfloat162*)(etb + b * FEAT) + lane * 2;
                const __nv_bfloat162* eps = (const __nv_bfloat162*)(esb + b * FEAT) + lane * 2;
                const float2 t0 = __bfloat1622float2(ept[0]);
                const float2 t1 = __bfloat1622float2(ept[1]);
                const float2 s0 = __bfloat1622float2(eps[0]);
                const float2 s1 = __bfloat1622float2(eps[1]);
                float dt = A[j].x * t0.x + A[j].y * t0.y + A[j].z * t1.x + A[j].w * t1.y;
                float ds = C[j].x * s0.x + C[j].y * s0.y + C[j].z * s1.x + C[j].w * s1.y;
                #pragma unroll
                for (int o = 16; o; o >>= 1) {
                    dt += __shfl_xor_sync(FULLM, dt, o);
                    ds += __shfl_xor_sync(FULLM, ds, o);
                }
                if (lane == 0) {
                    const float ot = __expf(dt * (1.0f / 0.07f));
                    const float os = __expf(ds * (1.0f / 0.07f));
                    g_out_t[b * PAD + k] = ot;
                    g_out_s[b * PAD + k] = os;
                    sumT += ot; sumS += os;
                }
            }
        }
    }

    if (lane == 0) { shT[w] = sumT; shS[w] = sumS; }
    __syncthreads();
    if (t == 0) {
        float aT = 0.f, aS = 0.f;
        #pragma unroll
        for (int i = 0; i < 32; ++i) { aT += shT[i]; aS += shS[i]; }
        atomicAdd(&g_sums[0], aT);
        atomicAdd(&g_sums[1], aS);
    }
}

// ---------------------------------------------------------------- memory copy-out (proven 6.7+ TB/s)
__global__ __launch_bounds__(256) void copy_kernel(const float* __restrict__ m1,
                                                   const float* __restrict__ m2,
                                                   float* __restrict__ out) {
    const int tid = blockIdx.x * blockDim.x + threadIdx.x;
    const int T = gridDim.x * blockDim.x;   // 4,000,000
    float4* o1b = (float4*)(out + 4);
    float4* o2b = (float4*)(out + 4 + MEMELEMS);
    #pragma unroll
    for (int s = 0; s < 4; ++s) {
        const int i = tid + s * T;
        if (i < N4) {
            float  h1 = __ldg(m1 + 3 + 4 * i);
            float4 v1 = __ldg((const float4*)(m1 + 4 + 4 * i));
            float  h2 = __ldg(m2 + 3 + 4 * i);
            float4 v2 = __ldg((const float4*)(m2 + 4 + 4 * i));
            o1b[i] = make_float4(h1, v1.x, v1.y, v1.z);
            o2b[i] = make_float4(h2, v2.x, v2.y, v2.z);
        }
    }
    if (tid == 0) {
        out[1] = m1[0]; out[2] = m1[1]; out[3] = m1[2];
        out[MEMELEMS] = m1[MEMELEMS - 1];
        out[1 + MEMELEMS] = m2[0]; out[2 + MEMELEMS] = m2[1]; out[3 + MEMELEMS] = m2[2];
        out[2 * MEMELEMS] = m2[MEMELEMS - 1];
    }
}

// ---------------------------------------------------------------- loss + update + finalize (R4-proven)
__global__ __launch_bounds__(256) void lossup_kernel(const int* __restrict__ idx,
                                                     const float* __restrict__ m1,
                                                     const float* __restrict__ m2,
                                                     float* __restrict__ out) {
    const int bid = blockIdx.x;
    if (bid < LOSS_BLOCKS) {
        const int b = bid / 5;
        const int k = ((bid % 5) * 256 + threadIdx.x) * 4;
        const float invZt = (float)TOTAL / ((float)NDATA * g_sums[0]);
        const float invZs = (float)TOTAL / ((float)NDATA * g_sums[1]);
        float acc = 0.f;
        if (k < KP1) {
            float4 vs = *((const float4*)(g_out_s + b * PAD + k));
            float4 vt = *((const float4*)(g_out_t + b * PAD + k));
            float xs[4] = {vs.x, vs.y, vs.z, vs.w};
            float xt[4] = {vt.x, vt.y, vt.z, vt.w};
            #pragma unroll
            for (int c = 0; c < 4; ++c) {
                if (k + c < KP1) {
                    float xS = xs[c] * invZs;
                    float xT = xt[c] * invZt;
                    if (k + c == 0) {
                        acc += logf(xS / (xS + MPN + EPSF)) + logf(xT / (xT + MPN + EPSF));
                    } else {
                        acc -= logf(1.0f + (xS + EPSF) * (1.0f / MPN));
                        acc -= logf(1.0f + (xT + EPSF) * (1.0f / MPN));
                    }
                }
            }
        }
        #pragma unroll
        for (int o = 16; o; o >>= 1) acc += __shfl_xor_sync(FULLM, acc, o);
        __shared__ float sh[8];
        const int lane = threadIdx.x & 31, w_ = threadIdx.x >> 5;
        if (lane == 0) sh[w_] = acc;
        __syncthreads();
        if (threadIdx.x == 0) {
            float tot = 0.f;
            #pragma unroll
            for (int i = 0; i < 8; ++i) tot += sh[i];
            atomicAdd(&g_sums[2], tot);
            __threadfence();
            int tk = atomicAdd(&g_ticket, 1);
            if (tk == LOSS_BLOCKS - 1)
                out[0] = -g_sums[2] / (float)BSZ;
        }
        return;
    }

    const int b = bid - LOSS_BLOCKS;
    const int t = threadIdx.x;
    if (t >= 128) return;
    float* o1 = out + 1;
    float* o2 = out + 1 + MEMELEMS;
    const int row = __ldg(idx + b);
    const size_t off = (size_t)row * FEAT + t;
    float v1 = __ldg(m1 + off) * 0.5f + g_es[b * FEAT + t] * 0.5f;
    float v2 = __ldg(m2 + off) * 0.5f + g_et[b * FEAT + t] * 0.5f;
    float s1 = v1 * v1, s2 = v2 * v2;
    #pragma unroll
    for (int o = 16; o; o >>= 1) {
        s1 += __shfl_xor_sync(FULLM, s1, o);
        s2 += __shfl_xor_sync(FULLM, s2, o);
    }
    __shared__ float sh1[4], sh2[4];
    const int lane = t & 31, w_ = t >> 5;
    if (lane == 0) { sh1[w_] = s1; sh2[w_] = s2; }
    __syncthreads();
    float t1 = sh1[0] + sh1[1] + sh1[2] + sh1[3];
    float t2 = sh2[0] + sh2[1] + sh2[2] + sh2[3];
    o1[off] = v1 / sqrtf(t1);
    o2[off] = v2 / sqrtf(t2);
}

// ---------------------------------------------------------------- launch
extern "C" void kernel_launch(void* const* d_in, const int* in_sizes, int n_in,
                              void* d_out, int out_size) {
    const float* f_s  = (const float*)d_in[0];
    const float* f_t  = (const float*)d_in[1];
    const int*   idx  = (const int*)  d_in[2];
    const int*   cidx = (const int*)  d_in[3];
    const float* W_s  = (const float*)d_in[4];
    const float* b_s  = (const float*)d_in[5];
    const float* W_t  = (const float*)d_in[6];
    const float* b_t  = (const float*)d_in[7];
    const float* m1   = (const float*)d_in[8];
    const float* m2   = (const float*)d_in[9];
    float* out = (float*)d_out;

    static int smem_set = 0;
    const int NCE_SMEM = 131072 + 32 * 128 * 4;   // 147456
    if (!smem_set) {
        cudaFuncSetAttribute(nce_kernel, cudaFuncAttributeMaxDynamicSharedMemorySize, NCE_SMEM);
        smem_set = 1;
    }

    embed_partial<<<1024, 128>>>(f_s, f_t, W_s, W_t);
    norm_scatter<<<1536, 128>>>(b_s, b_t, cidx);
    nce_kernel<<<NCE_CTAS, NCE_THR, NCE_SMEM>>>(m1, m2);
    copy_kernel<<<15625, 256>>>(m1, m2, out);
    lossup_kernel<<<LOSS_BLOCKS + BSZ, 256>>>(idx, m1, m2, out);
}

// round 8
// speedup vs baseline: 1.1692x; 1.1692x over previous
#include <cuda_runtime.h>
#include <cuda_bf16.h>
#include <cstdint>

#define BSZ    256
#define FEAT   128
#define KP1    4097
#define PAD    4100
#define NDATA  500000
#define SDIM   1024
#define TDIM   2048
#define MEMELEMS 64000000
#define TOTAL  (BSZ * KP1)        // 1,048,832
#define EPSF   1e-7f
#define MPN    (4096.0f / 500000.0f)
#define N4     15999999
#define KSPLIT 8
#define FULLM  0xffffffffu
#define CAP    24
#define LOSS_BLOCKS 1280
#define NCE_CTAS 148
#define NCE_THR  1024
#define NWARPS   (NCE_CTAS * 32)   // 4736
#define CHUNK    106               // 4736*106 = 502,016 >= NDATA
#define TILE     64
#define QCAP     256               // task queue per warp per tile (E~134, +10 sigma safe)

__device__ float g_es[BSZ * FEAT];
__device__ float g_et[BSZ * FEAT];
__device__ float g_part_s[KSPLIT * BSZ * FEAT];
__device__ float g_part_t[KSPLIT * BSZ * FEAT];
__device__ float g_out_s[BSZ * PAD];
__device__ float g_out_t[BSZ * PAD];
__device__ float g_sums[3];
__device__ int   g_ticket;
__device__ int   g_cnt[NDATA];
__device__ int   g_tasklist[NDATA * CAP];   // task id i = b*KP1 + k

// ---------------------------------------------------------------- embed partial (split-K) + cnt zeroing
__global__ __launch_bounds__(128) void embed_partial(const float* __restrict__ f_s,
                                                     const float* __restrict__ f_t,
                                                     const float* __restrict__ W_s,
                                                     const float* __restrict__ W_t) {
    {
        const int tid = blockIdx.x * 128 + threadIdx.x;   // 131072 threads
        for (int z = tid; z < NDATA; z += 1024 * 128) g_cnt[z] = 0;
        if (tid == 0) { g_sums[0] = 0.f; g_sums[1] = 0.f; g_sums[2] = 0.f; g_ticket = 0; }
    }
    __shared__ float fsh[4 * 256];
    const int bid = blockIdx.x;
    const bool is_t = bid >= 512;
    const int id = is_t ? bid - 512 : bid;
    const int rt = id >> 3;
    const int ks = id & 7;
    const int Kd = is_t ? TDIM : SDIM;
    const int kchunk = Kd / KSPLIT;
    const int k0 = ks * kchunk;
    const float* f = is_t ? f_t : f_s;
    const float* W = is_t ? W_t : W_s;
    float* part = is_t ? g_part_t : g_part_s;
    const int rows0 = rt * 4;
    const int t = threadIdx.x;

    #pragma unroll
    for (int r = 0; r < 4; ++r)
        for (int k = t; k < kchunk; k += 128)
            fsh[r * 256 + k] = f[(rows0 + r) * Kd + k0 + k];
    __syncthreads();

    float a0 = 0.f, a1 = 0.f, a2 = 0.f, a3 = 0.f;
    const float* Wp = W + (size_t)k0 * FEAT + t;
    #pragma unroll 8
    for (int k = 0; k < kchunk; ++k) {
        float w = Wp[(size_t)k * FEAT];
        a0 += fsh[k] * w;
        a1 += fsh[256 + k] * w;
        a2 += fsh[512 + k] * w;
        a3 += fsh[768 + k] * w;
    }
    part[(ks * BSZ + rows0 + 0) * FEAT + t] = a0;
    part[(ks * BSZ + rows0 + 1) * FEAT + t] = a1;
    part[(ks * BSZ + rows0 + 2) * FEAT + t] = a2;
    part[(ks * BSZ + rows0 + 3) * FEAT + t] = a3;
}

// ---------------------------------------------------------------- normalize + exact-row scatter
__global__ __launch_bounds__(128) void norm_scatter(const float* __restrict__ b_s,
                                                    const float* __restrict__ b_t,
                                                    const int* __restrict__ cidx) {
    const int bid = blockIdx.x;
    const int t = threadIdx.x;
    if (bid < 512) {
        const bool is_t = bid >= 256;
        const int row = is_t ? bid - 256 : bid;
        const float* part = is_t ? g_part_t : g_part_s;
        const float* bias = is_t ? b_t : b_s;
        float* out = is_t ? g_et : g_es;

        float v = bias[t];
        #pragma unroll
        for (int ks = 0; ks < KSPLIT; ++ks)
            v += part[(ks * BSZ + row) * FEAT + t];

        float sq = v * v;
        #pragma unroll
        for (int o = 16; o; o >>= 1) sq += __shfl_xor_sync(FULLM, sq, o);
        __shared__ float sh[4];
        const int lane = t & 31, w_ = t >> 5;
        if (lane == 0) sh[w_] = sq;
        __syncthreads();
        float tot = sh[0] + sh[1] + sh[2] + sh[3];
        out[row * FEAT + t] = v / sqrtf(tot);
        return;
    }
    const int tid = (bid - 512) * 128 + t;
    #pragma unroll 1
    for (int i = tid; i < TOTAL; i += 1024 * 128) {
        const int row = __ldg(cidx + i);
        const int pos = atomicAdd(&g_cnt[row], 1);
        if (pos < CAP)
            g_tasklist[(size_t)row * CAP + pos] = i;
    }
}

// ---------------------------------------------------------------- NCE: L1-dedup gather via row-sorted queue
// 148 CTAs x 1024 thr. smem: esb 64K | etb 64K | rowq 32K | iq 32K = 192K.
__global__ __launch_bounds__(NCE_THR, 1) void nce_kernel(const float* __restrict__ m1,
                                                         const float* __restrict__ m2) {
    extern __shared__ char sm[];
    __nv_bfloat16* esb = (__nv_bfloat16*)sm;
    __nv_bfloat16* etb = (__nv_bfloat16*)(sm + 65536);
    int* rowq_all = (int*)(sm + 131072);
    int* iq_all   = (int*)(sm + 131072 + 32768);
    __shared__ float shT[32], shS[32];

    const int t = threadIdx.x;
    for (int i = t; i < BSZ * FEAT; i += NCE_THR) {
        esb[i] = __float2bfloat16(g_es[i]);
        etb[i] = __float2bfloat16(g_et[i]);
    }
    __syncthreads();

    const int lane = t & 31;
    const int w = t >> 5;
    const int gw = blockIdx.x * 32 + w;
    const int r0 = gw * CHUNK;
    int* rowq = rowq_all + w * QCAP;
    int* iq   = iq_all   + w * QCAP;

    float sumT = 0.f, sumS = 0.f;

    #pragma unroll 1
    for (int tile0 = 0; tile0 < CHUNK; tile0 += TILE) {
        const int L = min(TILE, CHUNK - tile0);
        // ---- compaction: flatten (row, task) pairs for this tile into smem queue
        int total = 0;
        #pragma unroll 1
        for (int sub = 0; sub < L; sub += 32) {
            const int r = r0 + tile0 + sub + lane;
            int c = 0;
            if (sub + lane < L && r < NDATA) c = min(__ldg(&g_cnt[r]), CAP);
            int pre = c;
            #pragma unroll
            for (int o = 1; o < 32; o <<= 1) {
                int v = __shfl_up_sync(FULLM, pre, o);
                if (lane >= o) pre += v;
            }
            const int excl = total + pre - c;
            for (int d = 0; d < c; ++d) {
                rowq[excl + d] = r;
                iq[excl + d]   = __ldg(&g_tasklist[(size_t)r * CAP + d]);
            }
            total += __shfl_sync(FULLM, pre, 31);
        }
        __syncwarp();

        // ---- R4-style pipelined processing: groups of 4, 8 gathers in flight
        #pragma unroll 1
        for (int i0 = 0; i0 < total; i0 += 4) {
            const int m = min(4, total - i0);
            int rows[4], ii[4];
            #pragma unroll
            for (int j = 0; j < 4; ++j) {
                const int q = i0 + ((j < m) ? j : m - 1);
                rows[j] = rowq[q];
                ii[j]   = iq[q];
            }
            float4 A[4], C[4];
            #pragma unroll
            for (int j = 0; j < 4; ++j) {
                A[j] = __ldg((const float4*)m1 + (size_t)rows[j] * 32 + lane);
                C[j] = __ldg((const float4*)m2 + (size_t)rows[j] * 32 + lane);
            }
            int bs[4], ks[4];
            float dt[4], ds[4];
            #pragma unroll
            for (int j = 0; j < 4; ++j) {
                bs[j] = ii[j] / KP1;
                ks[j] = ii[j] - bs[j] * KP1;
                const __nv_bfloat162* ept = (const __nv_bfloat162*)(etb + bs[j] * FEAT) + lane * 2;
                const __nv_bfloat162* eps = (const __nv_bfloat162*)(esb + bs[j] * FEAT) + lane * 2;
                const float2 t0 = __bfloat1622float2(ept[0]);
                const float2 t1 = __bfloat1622float2(ept[1]);
                const float2 s0 = __bfloat1622float2(eps[0]);
                const float2 s1 = __bfloat1622float2(eps[1]);
                dt[j] = A[j].x * t0.x + A[j].y * t0.y + A[j].z * t1.x + A[j].w * t1.y;
                ds[j] = C[j].x * s0.x + C[j].y * s0.y + C[j].z * s1.x + C[j].w * s1.y;
            }
            #pragma unroll
            for (int o = 16; o; o >>= 1) {
                #pragma unroll
                for (int j = 0; j < 4; ++j) {
                    dt[j] += __shfl_xor_sync(FULLM, dt[j], o);
                    ds[j] += __shfl_xor_sync(FULLM, ds[j], o);
                }
            }
            if (lane == 0) {
                #pragma unroll
                for (int j = 0; j < 4; ++j) {
                    if (j < m) {
                        const float ot = __expf(dt[j] * (1.0f / 0.07f));
                        const float os = __expf(ds[j] * (1.0f / 0.07f));
                        g_out_t[bs[j] * PAD + ks[j]] = ot;
                        g_out_s[bs[j] * PAD + ks[j]] = os;
                        sumT += ot; sumS += os;
                    }
                }
            }
        }
    }

    if (lane == 0) { shT[w] = sumT; shS[w] = sumS; }
    __syncthreads();
    if (t == 0) {
        float aT = 0.f, aS = 0.f;
        #pragma unroll
        for (int i = 0; i < 32; ++i) { aT += shT[i]; aS += shS[i]; }
        atomicAdd(&g_sums[0], aT);
        atomicAdd(&g_sums[1], aS);
    }
}

// ---------------------------------------------------------------- memory copy-out (proven 6.7+ TB/s)
__global__ __launch_bounds__(256) void copy_kernel(const float* __restrict__ m1,
                                                   const float* __restrict__ m2,
                                                   float* __restrict__ out) {
    const int tid = blockIdx.x * blockDim.x + threadIdx.x;
    const int T = gridDim.x * blockDim.x;
    float4* o1b = (float4*)(out + 4);
    float4* o2b = (float4*)(out + 4 + MEMELEMS);
    #pragma unroll
    for (int s = 0; s < 4; ++s) {
        const int i = tid + s * T;
        if (i < N4) {
            float  h1 = __ldg(m1 + 3 + 4 * i);
            float4 v1 = __ldg((const float4*)(m1 + 4 + 4 * i));
            float  h2 = __ldg(m2 + 3 + 4 * i);
            float4 v2 = __ldg((const float4*)(m2 + 4 + 4 * i));
            o1b[i] = make_float4(h1, v1.x, v1.y, v1.z);
            o2b[i] = make_float4(h2, v2.x, v2.y, v2.z);
        }
    }
    if (tid == 0) {
        out[1] = m1[0]; out[2] = m1[1]; out[3] = m1[2];
        out[MEMELEMS] = m1[MEMELEMS - 1];
        out[1 + MEMELEMS] = m2[0]; out[2 + MEMELEMS] = m2[1]; out[3 + MEMELEMS] = m2[2];
        out[2 * MEMELEMS] = m2[MEMELEMS - 1];
    }
}

// ---------------------------------------------------------------- loss + update + finalize (R4-proven)
__global__ __launch_bounds__(256) void lossup_kernel(const int* __restrict__ idx,
                                                     const float* __restrict__ m1,
                                                     const float* __restrict__ m2,
                                                     float* __restrict__ out) {
    const int bid = blockIdx.x;
    if (bid < LOSS_BLOCKS) {
        const int b = bid / 5;
        const int k = ((bid % 5) * 256 + threadIdx.x) * 4;
        const float invZt = (float)TOTAL / ((float)NDATA * g_sums[0]);
        const float invZs = (float)TOTAL / ((float)NDATA * g_sums[1]);
        float acc = 0.f;
        if (k < KP1) {
            float4 vs = *((const float4*)(g_out_s + b * PAD + k));
            float4 vt = *((const float4*)(g_out_t + b * PAD + k));
            float xs[4] = {vs.x, vs.y, vs.z, vs.w};
            float xt[4] = {vt.x, vt.y, vt.z, vt.w};
            #pragma unroll
            for (int c = 0; c < 4; ++c) {
                if (k + c < KP1) {
                    float xS = xs[c] * invZs;
                    float xT = xt[c] * invZt;
                    if (k + c == 0) {
                        acc += logf(xS / (xS + MPN + EPSF)) + logf(xT / (xT + MPN + EPSF));
                    } else {
                        acc -= logf(1.0f + (xS + EPSF) * (1.0f / MPN));
                        acc -= logf(1.0f + (xT + EPSF) * (1.0f / MPN));
                    }
                }
            }
        }
        #pragma unroll
        for (int o = 16; o; o >>= 1) acc += __shfl_xor_sync(FULLM, acc, o);
        __shared__ float sh[8];
        const int lane = threadIdx.x & 31, w_ = threadIdx.x >> 5;
        if (lane == 0) sh[w_] = acc;
        __syncthreads();
        if (threadIdx.x == 0) {
            float tot = 0.f;
            #pragma unroll
            for (int i = 0; i < 8; ++i) tot += sh[i];
            atomicAdd(&g_sums[2], tot);
            __threadfence();
            int tk = atomicAdd(&g_ticket, 1);
            if (tk == LOSS_BLOCKS - 1)
                out[0] = -g_sums[2] / (float)BSZ;
        }
        return;
    }

    const int b = bid - LOSS_BLOCKS;
    const int t = threadIdx.x;
    if (t >= 128) return;
    float* o1 = out + 1;
    float* o2 = out + 1 + MEMELEMS;
    const int row = __ldg(idx + b);
    const size_t off = (size_t)row * FEAT + t;
    float v1 = __ldg(m1 + off) * 0.5f + g_es[b * FEAT + t] * 0.5f;
    float v2 = __ldg(m2 + off) * 0.5f + g_et[b * FEAT + t] * 0.5f;
    float s1 = v1 * v1, s2 = v2 * v2;
    #pragma unroll
    for (int o = 16; o; o >>= 1) {
        s1 += __shfl_xor_sync(FULLM, s1, o);
        s2 += __shfl_xor_sync(FULLM, s2, o);
    }
    __shared__ float sh1[4], sh2[4];
    const int lane = t & 31, w_ = t >> 5;
    if (lane == 0) { sh1[w_] = s1; sh2[w_] = s2; }
    __syncthreads();
    float t1 = sh1[0] + sh1[1] + sh1[2] + sh1[3];
    float t2 = sh2[0] + sh2[1] + sh2[2] + sh2[3];
    o1[off] = v1 / sqrtf(t1);
    o2[off] = v2 / sqrtf(t2);
}

// ---------------------------------------------------------------- launch
extern "C" void kernel_launch(void* const* d_in, const int* in_sizes, int n_in,
                              void* d_out, int out_size) {
    const float* f_s  = (const float*)d_in[0];
    const float* f_t  = (const float*)d_in[1];
    const int*   idx  = (const int*)  d_in[2];
    const int*   cidx = (const int*)  d_in[3];
    const float* W_s  = (const float*)d_in[4];
    const float* b_s  = (const float*)d_in[5];
    const float* W_t  = (const float*)d_in[6];
    const float* b_t  = (const float*)d_in[7];
    const float* m1   = (const float*)d_in[8];
    const float* m2   = (const float*)d_in[9];
    float* out = (float*)d_out;

    static int smem_set = 0;
    const int NCE_SMEM = 65536 * 2 + 32768 * 2;   // 196608
    if (!smem_set) {
        cudaFuncSetAttribute(nce_kernel, cudaFuncAttributeMaxDynamicSharedMemorySize, NCE_SMEM);
        smem_set = 1;
    }

    embed_partial<<<1024, 128>>>(f_s, f_t, W_s, W_t);
    norm_scatter<<<1536, 128>>>(b_s, b_t, cidx);
    nce_kernel<<<NCE_CTAS, NCE_THR, NCE_SMEM>>>(m1, m2);
    copy_kernel<<<15625, 256>>>(m1, m2, out);
    lossup_kernel<<<LOSS_BLOCKS + BSZ, 256>>>(idx, m1, m2, out);
}

// round 9
// speedup vs baseline: 1.2309x; 1.0528x over previous
#include <cuda_runtime.h>
#include <cuda_bf16.h>
#include <cstdint>

#define BSZ    256
#define FEAT   128
#define KP1    4097
#define PAD    4100
#define NDATA  500000
#define SDIM   1024
#define TDIM   2048
#define MEMELEMS 64000000
#define TOTAL  (BSZ * KP1)        // 1,048,832
#define EPSF   1e-7f
#define MPN    (4096.0f / 500000.0f)
#define N4     15999999
#define KSPLIT 8
#define FULLM  0xffffffffu
#define CAP    24
#define LOSS_BLOCKS 1280
#define NCE_CTAS 148
#define NCE_THR  1024
#define NWARPS   (NCE_CTAS * 32)   // 4736
#define CHUNK    106               // 4736*106 = 502,016 >= NDATA
#define TILE     64
#define QCAP     256
#define NCHUNKS  16384             // copy chunks of 1024 float4 (16,777,216 >= N4)

__device__ float g_es[BSZ * FEAT];
__device__ float g_et[BSZ * FEAT];
__device__ float g_part_s[KSPLIT * BSZ * FEAT];
__device__ float g_part_t[KSPLIT * BSZ * FEAT];
__device__ float g_out_s[BSZ * PAD];
__device__ float g_out_t[BSZ * PAD];
__device__ float g_sums[3];        // static zero-init; self-cleaned each launch
__device__ int   g_ticket;
__device__ int   g_copyctr;
__device__ int   g_cnt[NDATA];
__device__ int   g_tasklist[NDATA * CAP];

// ---------------------------------------------------------------- embed partial + scatter (fused launch)
// bid < 1024: split-K embed partials. bid >= 1024 (1024 blocks): exact-row scatter.
__global__ __launch_bounds__(128) void embed_scatter(const float* __restrict__ f_s,
                                                     const float* __restrict__ f_t,
                                                     const float* __restrict__ W_s,
                                                     const float* __restrict__ W_t,
                                                     const int* __restrict__ cidx) {
    const int bid = blockIdx.x;
    const int t = threadIdx.x;
    if (bid >= 1024) {
        const int tid = (bid - 1024) * 128 + t;
        #pragma unroll 1
        for (int i = tid; i < TOTAL; i += 1024 * 128) {
            const int row = __ldg(cidx + i);
            const int pos = atomicAdd(&g_cnt[row], 1);
            if (pos < CAP)
                g_tasklist[(size_t)row * CAP + pos] = i;
        }
        return;
    }
    __shared__ float fsh[4 * 256];
    const bool is_t = bid >= 512;
    const int id = is_t ? bid - 512 : bid;
    const int rt = id >> 3;
    const int ks = id & 7;
    const int Kd = is_t ? TDIM : SDIM;
    const int kchunk = Kd / KSPLIT;
    const int k0 = ks * kchunk;
    const float* f = is_t ? f_t : f_s;
    const float* W = is_t ? W_t : W_s;
    float* part = is_t ? g_part_t : g_part_s;
    const int rows0 = rt * 4;

    #pragma unroll
    for (int r = 0; r < 4; ++r)
        for (int k = t; k < kchunk; k += 128)
            fsh[r * 256 + k] = f[(rows0 + r) * Kd + k0 + k];
    __syncthreads();

    float a0 = 0.f, a1 = 0.f, a2 = 0.f, a3 = 0.f;
    const float* Wp = W + (size_t)k0 * FEAT + t;
    #pragma unroll 8
    for (int k = 0; k < kchunk; ++k) {
        float w = Wp[(size_t)k * FEAT];
        a0 += fsh[k] * w;
        a1 += fsh[256 + k] * w;
        a2 += fsh[512 + k] * w;
        a3 += fsh[768 + k] * w;
    }
    part[(ks * BSZ + rows0 + 0) * FEAT + t] = a0;
    part[(ks * BSZ + rows0 + 1) * FEAT + t] = a1;
    part[(ks * BSZ + rows0 + 2) * FEAT + t] = a2;
    part[(ks * BSZ + rows0 + 3) * FEAT + t] = a3;
}

// ---------------------------------------------------------------- normalize
__global__ __launch_bounds__(128) void norm_kernel(const float* __restrict__ b_s,
                                                   const float* __restrict__ b_t) {
    const int bid = blockIdx.x;
    const int t = threadIdx.x;
    const bool is_t = bid >= 256;
    const int row = is_t ? bid - 256 : bid;
    const float* part = is_t ? g_part_t : g_part_s;
    const float* bias = is_t ? b_t : b_s;
    float* out = is_t ? g_et : g_es;

    float v = bias[t];
    #pragma unroll
    for (int ks = 0; ks < KSPLIT; ++ks)
        v += part[(ks * BSZ + row) * FEAT + t];

    float sq = v * v;
    #pragma unroll
    for (int o = 16; o; o >>= 1) sq += __shfl_xor_sync(FULLM, sq, o);
    __shared__ float sh[4];
    const int lane = t & 31, w_ = t >> 5;
    if (lane == 0) sh[w_] = sq;
    __syncthreads();
    float tot = sh[0] + sh[1] + sh[2] + sh[3];
    out[row * FEAT + t] = v / sqrtf(tot);
}

// ---------------------------------------------------------------- FUSED: nce (dedup) + copy (work-steal)
// 148 CTAs x 1024 thr. smem: esb 64K | etb 64K | rowq 32K | iq 32K = 192K.
__global__ __launch_bounds__(NCE_THR, 1) void nce_copy_kernel(const float* __restrict__ m1,
                                                              const float* __restrict__ m2,
                                                              float* __restrict__ out) {
    extern __shared__ char sm[];
    __nv_bfloat16* esb = (__nv_bfloat16*)sm;
    __nv_bfloat16* etb = (__nv_bfloat16*)(sm + 65536);
    int* rowq_all = (int*)(sm + 131072);
    int* iq_all   = (int*)(sm + 131072 + 32768);
    __shared__ float shT[32], shS[32];

    const int t = threadIdx.x;
    if (blockIdx.x == 0 && t == 0) {
        out[1] = m1[0]; out[2] = m1[1]; out[3] = m1[2];
        out[MEMELEMS] = m1[MEMELEMS - 1];
        out[1 + MEMELEMS] = m2[0]; out[2 + MEMELEMS] = m2[1]; out[3 + MEMELEMS] = m2[2];
        out[2 * MEMELEMS] = m2[MEMELEMS - 1];
    }
    for (int i = t; i < BSZ * FEAT; i += NCE_THR) {
        esb[i] = __float2bfloat16(g_es[i]);
        etb[i] = __float2bfloat16(g_et[i]);
    }
    __syncthreads();

    const int lane = t & 31;
    const int w = t >> 5;
    const int gw = blockIdx.x * 32 + w;
    const int r0 = gw * CHUNK;
    int* rowq = rowq_all + w * QCAP;
    int* iq   = iq_all   + w * QCAP;

    float sumT = 0.f, sumS = 0.f;

    // ---------------- phase A: dedup nce over this warp's fixed row chunk
    #pragma unroll 1
    for (int tile0 = 0; tile0 < CHUNK; tile0 += TILE) {
        const int L = min(TILE, CHUNK - tile0);
        int total = 0;
        #pragma unroll 1
        for (int sub = 0; sub < L; sub += 32) {
            const int r = r0 + tile0 + sub + lane;
            int c = 0;
            if (sub + lane < L && r < NDATA) c = min(__ldg(&g_cnt[r]), CAP);
            int pre = c;
            #pragma unroll
            for (int o = 1; o < 32; o <<= 1) {
                int v = __shfl_up_sync(FULLM, pre, o);
                if (lane >= o) pre += v;
            }
            const int excl = total + pre - c;
            for (int d = 0; d < c; ++d) {
                rowq[excl + d] = r;
                iq[excl + d]   = __ldg(&g_tasklist[(size_t)r * CAP + d]);
            }
            total += __shfl_sync(FULLM, pre, 31);
        }
        __syncwarp();

        #pragma unroll 1
        for (int i0 = 0; i0 < total; i0 += 4) {
            const int m = min(4, total - i0);
            int rows[4], ii[4];
            #pragma unroll
            for (int j = 0; j < 4; ++j) {
                const int q = i0 + ((j < m) ? j : m - 1);
                rows[j] = rowq[q];
                ii[j]   = iq[q];
            }
            float4 A[4], C[4];
            #pragma unroll
            for (int j = 0; j < 4; ++j) {
                A[j] = __ldg((const float4*)m1 + (size_t)rows[j] * 32 + lane);
                C[j] = __ldg((const float4*)m2 + (size_t)rows[j] * 32 + lane);
            }
            int bs[4], ks[4];
            float dt[4], ds[4];
            #pragma unroll
            for (int j = 0; j < 4; ++j) {
                bs[j] = ii[j] / KP1;
                ks[j] = ii[j] - bs[j] * KP1;
                const __nv_bfloat162* ept = (const __nv_bfloat162*)(etb + bs[j] * FEAT) + lane * 2;
                const __nv_bfloat162* eps = (const __nv_bfloat162*)(esb + bs[j] * FEAT) + lane * 2;
                const float2 t0 = __bfloat1622float2(ept[0]);
                const float2 t1 = __bfloat1622float2(ept[1]);
                const float2 s0 = __bfloat1622float2(eps[0]);
                const float2 s1 = __bfloat1622float2(eps[1]);
                dt[j] = A[j].x * t0.x + A[j].y * t0.y + A[j].z * t1.x + A[j].w * t1.y;
                ds[j] = C[j].x * s0.x + C[j].y * s0.y + C[j].z * s1.x + C[j].w * s1.y;
            }
            #pragma unroll
            for (int o = 16; o; o >>= 1) {
                #pragma unroll
                for (int j = 0; j < 4; ++j) {
                    dt[j] += __shfl_xor_sync(FULLM, dt[j], o);
                    ds[j] += __shfl_xor_sync(FULLM, ds[j], o);
                }
            }
            if (lane == 0) {
                #pragma unroll
                for (int j = 0; j < 4; ++j) {
                    if (j < m) {
                        const float ot = __expf(dt[j] * (1.0f / 0.07f));
                        const float os = __expf(ds[j] * (1.0f / 0.07f));
                        g_out_t[bs[j] * PAD + ks[j]] = ot;
                        g_out_s[bs[j] * PAD + ks[j]] = os;
                        sumT += ot; sumS += os;
                    }
                }
            }
        }
    }

    if (lane == 0) { shT[w] = sumT; shS[w] = sumS; }

    // ---------------- phase B: warp-level work-stealing copy
    float4* o1b = (float4*)(out + 4);
    float4* o2b = (float4*)(out + 4 + MEMELEMS);
    for (;;) {
        int c = 0;
        if (lane == 0) c = atomicAdd(&g_copyctr, 1);
        c = __shfl_sync(FULLM, c, 0);
        if (c >= NCHUNKS) break;
        const int base = (c << 10) + lane;
        #pragma unroll 4
        for (int j = 0; j < 32; ++j) {
            const int i = base + (j << 5);
            if (i < N4) {
                float  h1 = __ldg(m1 + 3 + 4 * i);
                float4 v1 = __ldg((const float4*)(m1 + 4 + 4 * i));
                float  h2 = __ldg(m2 + 3 + 4 * i);
                float4 v2 = __ldg((const float4*)(m2 + 4 + 4 * i));
                o1b[i] = make_float4(h1, v1.x, v1.y, v1.z);
                o2b[i] = make_float4(h2, v2.x, v2.y, v2.z);
            }
        }
    }

    __syncthreads();
    if (t == 0) {
        float aT = 0.f, aS = 0.f;
        #pragma unroll
        for (int i = 0; i < 32; ++i) { aT += shT[i]; aS += shS[i]; }
        atomicAdd(&g_sums[0], aT);
        atomicAdd(&g_sums[1], aS);
    }
}

// ---------------------------------------------------------------- loss + update + finalize + cleanup
__global__ __launch_bounds__(256) void lossup_kernel(const int* __restrict__ idx,
                                                     const float* __restrict__ m1,
                                                     const float* __restrict__ m2,
                                                     float* __restrict__ out) {
    // cleanup for next graph replay: zero g_cnt (consumed this launch)
    {
        const int tidg = blockIdx.x * 256 + threadIdx.x;
        for (int z = tidg; z < NDATA; z += (LOSS_BLOCKS + BSZ) * 256) g_cnt[z] = 0;
    }
    const int bid = blockIdx.x;
    if (bid < LOSS_BLOCKS) {
        const int b = bid / 5;
        const int k = ((bid % 5) * 256 + threadIdx.x) * 4;
        const float invZt = (float)TOTAL / ((float)NDATA * g_sums[0]);
        const float invZs = (float)TOTAL / ((float)NDATA * g_sums[1]);
        float acc = 0.f;
        if (k < KP1) {
            float4 vs = *((const float4*)(g_out_s + b * PAD + k));
            float4 vt = *((const float4*)(g_out_t + b * PAD + k));
            float xs[4] = {vs.x, vs.y, vs.z, vs.w};
            float xt[4] = {vt.x, vt.y, vt.z, vt.w};
            #pragma unroll
            for (int c = 0; c < 4; ++c) {
                if (k + c < KP1) {
                    float xS = xs[c] * invZs;
                    float xT = xt[c] * invZt;
                    if (k + c == 0) {
                        acc += logf(xS / (xS + MPN + EPSF)) + logf(xT / (xT + MPN + EPSF));
                    } else {
                        acc -= logf(1.0f + (xS + EPSF) * (1.0f / MPN));
                        acc -= logf(1.0f + (xT + EPSF) * (1.0f / MPN));
                    }
                }
            }
        }
        #pragma unroll
        for (int o = 16; o; o >>= 1) acc += __shfl_xor_sync(FULLM, acc, o);
        __shared__ float sh[8];
        const int lane = threadIdx.x & 31, w_ = threadIdx.x >> 5;
        if (lane == 0) sh[w_] = acc;
        __syncthreads();
        if (threadIdx.x == 0) {
            float tot = 0.f;
            #pragma unroll
            for (int i = 0; i < 8; ++i) tot += sh[i];
            atomicAdd(&g_sums[2], tot);
            __threadfence();
            int tk = atomicAdd(&g_ticket, 1);
            if (tk == LOSS_BLOCKS - 1) {
                out[0] = -g_sums[2] / (float)BSZ;
                // self-clean counters for next replay (all loss blocks are done)
                g_sums[0] = 0.f; g_sums[1] = 0.f; g_sums[2] = 0.f;
                g_ticket = 0; g_copyctr = 0;
            }
        }
        return;
    }

    const int b = bid - LOSS_BLOCKS;
    const int t = threadIdx.x;
    if (t >= 128) return;
    float* o1 = out + 1;
    float* o2 = out + 1 + MEMELEMS;
    const int row = __ldg(idx + b);
    const size_t off = (size_t)row * FEAT + t;
    float v1 = __ldg(m1 + off) * 0.5f + g_es[b * FEAT + t] * 0.5f;
    float v2 = __ldg(m2 + off) * 0.5f + g_et[b * FEAT + t] * 0.5f;
    float s1 = v1 * v1, s2 = v2 * v2;
    #pragma unroll
    for (int o = 16; o; o >>= 1) {
        s1 += __shfl_xor_sync(FULLM, s1, o);
        s2 += __shfl_xor_sync(FULLM, s2, o);
    }
    __shared__ float sh1[4], sh2[4];
    const int lane = t & 31, w_ = t >> 5;
    if (lane == 0) { sh1[w_] = s1; sh2[w_] = s2; }
    __syncthreads();
    float t1 = sh1[0] + sh1[1] + sh1[2] + sh1[3];
    float t2 = sh2[0] + sh2[1] + sh2[2] + sh2[3];
    o1[off] = v1 / sqrtf(t1);
    o2[off] = v2 / sqrtf(t2);
}

// ---------------------------------------------------------------- launch
extern "C" void kernel_launch(void* const* d_in, const int* in_sizes, int n_in,
                              void* d_out, int out_size) {
    const float* f_s  = (const float*)d_in[0];
    const float* f_t  = (const float*)d_in[1];
    const int*   idx  = (const int*)  d_in[2];
    const int*   cidx = (const int*)  d_in[3];
    const float* W_s  = (const float*)d_in[4];
    const float* b_s  = (const float*)d_in[5];
    const float* W_t  = (const float*)d_in[6];
    const float* b_t  = (const float*)d_in[7];
    const float* m1   = (const float*)d_in[8];
    const float* m2   = (const float*)d_in[9];
    float* out = (float*)d_out;

    static int smem_set = 0;
    const int NCE_SMEM = 65536 * 2 + 32768 * 2;   // 196608
    if (!smem_set) {
        cudaFuncSetAttribute(nce_copy_kernel, cudaFuncAttributeMaxDynamicSharedMemorySize, NCE_SMEM);
        smem_set = 1;
    }

    embed_scatter<<<2048, 128>>>(f_s, f_t, W_s, W_t, cidx);
    norm_kernel<<<512, 128>>>(b_s, b_t);
    nce_copy_kernel<<<NCE_CTAS, NCE_THR, NCE_SMEM>>>(m1, m2, out);
    lossup_kernel<<<LOSS_BLOCKS + BSZ, 256>>>(idx, m1, m2, out);
}

// round 10
// speedup vs baseline: 1.5322x; 1.2448x over previous
#include <cuda_runtime.h>
#include <cuda_bf16.h>
#include <cstdint>

#define BSZ    256
#define FEAT   128
#define KP1    4097
#define PAD    4100
#define NDATA  500000
#define SDIM   1024
#define TDIM   2048
#define MEMELEMS 64000000
#define TOTAL  (BSZ * KP1)        // 1,048,832
#define EPSF   1e-7f
#define MPN    (4096.0f / 500000.0f)
#define KSPLIT 8
#define FULLM  0xffffffffu
#define CAP    24
#define LOSS_BLOCKS 1280
#define MEGA_CTAS 148
#define MEGA_THR  1024
#define NWARPS   (MEGA_CTAS * 32)  // 4736
#define CHUNK    106               // 4736*106 = 502,016 >= NDATA

__device__ float g_es[BSZ * FEAT];
__device__ float g_et[BSZ * FEAT];
__device__ float g_part_s[KSPLIT * BSZ * FEAT];
__device__ float g_part_t[KSPLIT * BSZ * FEAT];
__device__ float g_out_s[BSZ * PAD];
__device__ float g_out_t[BSZ * PAD];
__device__ float g_sums[3];        // static zero-init; self-cleaned each launch
__device__ int   g_ticket;
__device__ int   g_cnt[NDATA];     // static zero-init; self-cleaned in lossup
__device__ int   g_tasklist[NDATA * CAP];

// ---------------------------------------------------------------- embed partial + scatter (fused launch)
__global__ __launch_bounds__(128) void embed_scatter(const float* __restrict__ f_s,
                                                     const float* __restrict__ f_t,
                                                     const float* __restrict__ W_s,
                                                     const float* __restrict__ W_t,
                                                     const int* __restrict__ cidx) {
    const int bid = blockIdx.x;
    const int t = threadIdx.x;
    if (bid >= 1024) {
        const int tid = (bid - 1024) * 128 + t;
        #pragma unroll 1
        for (int i = tid; i < TOTAL; i += 1024 * 128) {
            const int row = __ldg(cidx + i);
            const int pos = atomicAdd(&g_cnt[row], 1);
            if (pos < CAP)
                g_tasklist[(size_t)row * CAP + pos] = i;
        }
        return;
    }
    __shared__ float fsh[4 * 256];
    const bool is_t = bid >= 512;
    const int id = is_t ? bid - 512 : bid;
    const int rt = id >> 3;
    const int ks = id & 7;
    const int Kd = is_t ? TDIM : SDIM;
    const int kchunk = Kd / KSPLIT;
    const int k0 = ks * kchunk;
    const float* f = is_t ? f_t : f_s;
    const float* W = is_t ? W_t : W_s;
    float* part = is_t ? g_part_t : g_part_s;
    const int rows0 = rt * 4;

    #pragma unroll
    for (int r = 0; r < 4; ++r)
        for (int k = t; k < kchunk; k += 128)
            fsh[r * 256 + k] = f[(rows0 + r) * Kd + k0 + k];
    __syncthreads();

    float a0 = 0.f, a1 = 0.f, a2 = 0.f, a3 = 0.f;
    const float* Wp = W + (size_t)k0 * FEAT + t;
    #pragma unroll 8
    for (int k = 0; k < kchunk; ++k) {
        float w = Wp[(size_t)k * FEAT];
        a0 += fsh[k] * w;
        a1 += fsh[256 + k] * w;
        a2 += fsh[512 + k] * w;
        a3 += fsh[768 + k] * w;
    }
    part[(ks * BSZ + rows0 + 0) * FEAT + t] = a0;
    part[(ks * BSZ + rows0 + 1) * FEAT + t] = a1;
    part[(ks * BSZ + rows0 + 2) * FEAT + t] = a2;
    part[(ks * BSZ + rows0 + 3) * FEAT + t] = a3;
}

// ---------------------------------------------------------------- normalize
__global__ __launch_bounds__(128) void norm_kernel(const float* __restrict__ b_s,
                                                   const float* __restrict__ b_t) {
    const int bid = blockIdx.x;
    const int t = threadIdx.x;
    const bool is_t = bid >= 256;
    const int row = is_t ? bid - 256 : bid;
    const float* part = is_t ? g_part_t : g_part_s;
    const float* bias = is_t ? b_t : b_s;
    float* out = is_t ? g_et : g_es;

    float v = bias[t];
    #pragma unroll
    for (int ks = 0; ks < KSPLIT; ++ks)
        v += part[(ks * BSZ + row) * FEAT + t];

    float sq = v * v;
    #pragma unroll
    for (int o = 16; o; o >>= 1) sq += __shfl_xor_sync(FULLM, sq, o);
    __shared__ float sh[4];
    const int lane = t & 31, w_ = t >> 5;
    if (lane == 0) sh[w_] = sq;
    __syncthreads();
    float tot = sh[0] + sh[1] + sh[2] + sh[3];
    out[row * FEAT + t] = v / sqrtf(tot);
}

// ---------------------------------------------------------------- MEGA: single-pass row sweep
// Each warp sweeps CHUNK contiguous rows. Per row: ONE read of m1/m2 serves
// BOTH the copy-out (shifted float4 stores via shfl carry) AND all NCE dots.
__global__ __launch_bounds__(MEGA_THR, 1) void mega_kernel(const float* __restrict__ m1,
                                                           const float* __restrict__ m2,
                                                           float* __restrict__ out) {
    extern __shared__ char sm[];
    __nv_bfloat16* esb = (__nv_bfloat16*)sm;              // 64 KB
    __nv_bfloat16* etb = (__nv_bfloat16*)(sm + 65536);    // 64 KB
    __shared__ float shT[32], shS[32];

    const int t = threadIdx.x;
    for (int i = t; i < BSZ * FEAT; i += MEGA_THR) {
        esb[i] = __float2bfloat16(g_es[i]);
        etb[i] = __float2bfloat16(g_et[i]);
    }
    __syncthreads();

    const int lane = t & 31;
    const int w = t >> 5;
    const int gw = blockIdx.x * 32 + w;
    const int r0 = gw * CHUNK;
    const int rend = min(r0 + CHUNK, NDATA);

    float sumT = 0.f, sumS = 0.f;

    if (r0 < rend) {
        float4* o1b = (float4*)out;
        float4* o2b = (float4*)(out + MEMELEMS);

        float carry1 = 0.f, carry2 = 0.f;
        if (r0 > 0 && lane == 0) {
            carry1 = __ldg(m1 + (size_t)r0 * FEAT - 1);
            carry2 = __ldg(m2 + (size_t)r0 * FEAT - 1);
        }

        // prefetch first row
        float4 A = __ldg((const float4*)m1 + (size_t)r0 * 32 + lane);
        float4 C = __ldg((const float4*)m2 + (size_t)r0 * 32 + lane);
        int cnt = __ldg(&g_cnt[r0]);

        #pragma unroll 1
        for (int r = r0; r < rend; ++r) {
            // prefetch next row
            float4 A2, C2; int cnt2 = 0;
            if (r + 1 < rend) {
                A2 = __ldg((const float4*)m1 + (size_t)(r + 1) * 32 + lane);
                C2 = __ldg((const float4*)m2 + (size_t)(r + 1) * 32 + lane);
                cnt2 = __ldg(&g_cnt[r + 1]);
            }

            // ---- NCE dots for this row's tasks
            const int c = min(cnt, CAP);
            if (c > 0) {
                int rec = 0;
                if (lane < c) rec = __ldg(&g_tasklist[(size_t)r * CAP + lane]);
                #pragma unroll 1
                for (int tt = 0; tt < c; ++tt) {
                    const int i = __shfl_sync(FULLM, rec, tt);
                    const int b = i / KP1;
                    const int k = i - b * KP1;
                    const __nv_bfloat162* ept = (const __nv_bfloat162*)(etb + b * FEAT) + lane * 2;
                    const __nv_bfloat162* eps = (const __nv_bfloat162*)(esb + b * FEAT) + lane * 2;
                    const float2 t0 = __bfloat1622float2(ept[0]);
                    const float2 t1 = __bfloat1622float2(ept[1]);
                    const float2 s0 = __bfloat1622float2(eps[0]);
                    const float2 s1 = __bfloat1622float2(eps[1]);
                    float dt = A.x * t0.x + A.y * t0.y + A.z * t1.x + A.w * t1.y;
                    float ds = C.x * s0.x + C.y * s0.y + C.z * s1.x + C.w * s1.y;
                    #pragma unroll
                    for (int o = 16; o; o >>= 1) {
                        dt += __shfl_xor_sync(FULLM, dt, o);
                        ds += __shfl_xor_sync(FULLM, ds, o);
                    }
                    if (lane == 0) {
                        const float ot = __expf(dt * (1.0f / 0.07f));
                        const float os = __expf(ds * (1.0f / 0.07f));
                        g_out_t[b * PAD + k] = ot;
                        g_out_s[b * PAD + k] = os;
                        sumT += ot; sumS += os;
                    }
                }
            }

            // ---- copy-out (shifted by +1 element): aligned float4 stores
            float p1 = __shfl_up_sync(FULLM, A.w, 1);
            float p2 = __shfl_up_sync(FULLM, C.w, 1);
            if (lane == 0) { p1 = carry1; p2 = carry2; }
            const int ci = r * 32 + lane;
            if (r == 0 && lane == 0) {
                // protect out[0] (loss) and out[MEMELEMS] (m1 tail slot)
                out[1] = A.x; out[2] = A.y; out[3] = A.z;
                out[MEMELEMS + 1] = C.x; out[MEMELEMS + 2] = C.y; out[MEMELEMS + 3] = C.z;
            } else {
                o1b[ci] = make_float4(p1, A.x, A.y, A.z);
                o2b[ci] = make_float4(p2, C.x, C.y, C.z);
            }
            if (r == NDATA - 1 && lane == 31) {
                out[MEMELEMS] = A.w;                 // m1 last element
                out[(size_t)2 * MEMELEMS] = C.w;     // m2 last element
            }
            carry1 = __shfl_sync(FULLM, A.w, 31);
            carry2 = __shfl_sync(FULLM, C.w, 31);
            A = A2; C = C2; cnt = cnt2;
        }
    }

    if (lane == 0) { shT[w] = sumT; shS[w] = sumS; }
    __syncthreads();
    if (t == 0) {
        float aT = 0.f, aS = 0.f;
        #pragma unroll
        for (int i = 0; i < 32; ++i) { aT += shT[i]; aS += shS[i]; }
        atomicAdd(&g_sums[0], aT);
        atomicAdd(&g_sums[1], aS);
    }
}

// ---------------------------------------------------------------- loss + update + finalize + cleanup
__global__ __launch_bounds__(256) void lossup_kernel(const int* __restrict__ idx,
                                                     const float* __restrict__ m1,
                                                     const float* __restrict__ m2,
                                                     float* __restrict__ out) {
    // cleanup for next graph replay
    {
        const int tidg = blockIdx.x * 256 + threadIdx.x;
        for (int z = tidg; z < NDATA; z += (LOSS_BLOCKS + BSZ) * 256) g_cnt[z] = 0;
    }
    const int bid = blockIdx.x;
    if (bid < LOSS_BLOCKS) {
        const int b = bid / 5;
        const int k = ((bid % 5) * 256 + threadIdx.x) * 4;
        const float invZt = (float)TOTAL / ((float)NDATA * g_sums[0]);
        const float invZs = (float)TOTAL / ((float)NDATA * g_sums[1]);
        float acc = 0.f;
        if (k < KP1) {
            float4 vs = *((const float4*)(g_out_s + b * PAD + k));
            float4 vt = *((const float4*)(g_out_t + b * PAD + k));
            float xs[4] = {vs.x, vs.y, vs.z, vs.w};
            float xt[4] = {vt.x, vt.y, vt.z, vt.w};
            #pragma unroll
            for (int c = 0; c < 4; ++c) {
                if (k + c < KP1) {
                    float xS = xs[c] * invZs;
                    float xT = xt[c] * invZt;
                    if (k + c == 0) {
                        acc += logf(xS / (xS + MPN + EPSF)) + logf(xT / (xT + MPN + EPSF));
                    } else {
                        acc -= logf(1.0f + (xS + EPSF) * (1.0f / MPN));
                        acc -= logf(1.0f + (xT + EPSF) * (1.0f / MPN));
                    }
                }
            }
        }
        #pragma unroll
        for (int o = 16; o; o >>= 1) acc += __shfl_xor_sync(FULLM, acc, o);
        __shared__ float sh[8];
        const int lane = threadIdx.x & 31, w_ = threadIdx.x >> 5;
        if (lane == 0) sh[w_] = acc;
        __syncthreads();
        if (threadIdx.x == 0) {
            float tot = 0.f;
            #pragma unroll
            for (int i = 0; i < 8; ++i) tot += sh[i];
            atomicAdd(&g_sums[2], tot);
            __threadfence();
            int tk = atomicAdd(&g_ticket, 1);
            if (tk == LOSS_BLOCKS - 1) {
                out[0] = -g_sums[2] / (float)BSZ;
                g_sums[0] = 0.f; g_sums[1] = 0.f; g_sums[2] = 0.f;
                g_ticket = 0;
            }
        }
        return;
    }

    const int b = bid - LOSS_BLOCKS;
    const int t = threadIdx.x;
    if (t >= 128) return;
    float* o1 = out + 1;
    float* o2 = out + 1 + MEMELEMS;
    const int row = __ldg(idx + b);
    const size_t off = (size_t)row * FEAT + t;
    float v1 = __ldg(m1 + off) * 0.5f + g_es[b * FEAT + t] * 0.5f;
    float v2 = __ldg(m2 + off) * 0.5f + g_et[b * FEAT + t] * 0.5f;
    float s1 = v1 * v1, s2 = v2 * v2;
    #pragma unroll
    for (int o = 16; o; o >>= 1) {
        s1 += __shfl_xor_sync(FULLM, s1, o);
        s2 += __shfl_xor_sync(FULLM, s2, o);
    }
    __shared__ float sh1[4], sh2[4];
    const int lane = t & 31, w_ = t >> 5;
    if (lane == 0) { sh1[w_] = s1; sh2[w_] = s2; }
    __syncthreads();
    float t1 = sh1[0] + sh1[1] + sh1[2] + sh1[3];
    float t2 = sh2[0] + sh2[1] + sh2[2] + sh2[3];
    o1[off] = v1 / sqrtf(t1);
    o2[off] = v2 / sqrtf(t2);
}

// ---------------------------------------------------------------- launch
extern "C" void kernel_launch(void* const* d_in, const int* in_sizes, int n_in,
                              void* d_out, int out_size) {
    const float* f_s  = (const float*)d_in[0];
    const float* f_t  = (const float*)d_in[1];
    const int*   idx  = (const int*)  d_in[2];
    const int*   cidx = (const int*)  d_in[3];
    const float* W_s  = (const float*)d_in[4];
    const float* b_s  = (const float*)d_in[5];
    const float* W_t  = (const float*)d_in[6];
    const float* b_t  = (const float*)d_in[7];
    const float* m1   = (const float*)d_in[8];
    const float* m2   = (const float*)d_in[9];
    float* out = (float*)d_out;

    static int smem_set = 0;
    const int MEGA_SMEM = 131072;
    if (!smem_set) {
        cudaFuncSetAttribute(mega_kernel, cudaFuncAttributeMaxDynamicSharedMemorySize, MEGA_SMEM);
        smem_set = 1;
    }

    embed_scatter<<<2048, 128>>>(f_s, f_t, W_s, W_t, cidx);
    norm_kernel<<<512, 128>>>(b_s, b_t);
    mega_kernel<<<MEGA_CTAS, MEGA_THR, MEGA_SMEM>>>(m1, m2, out);
    lossup_kernel<<<LOSS_BLOCKS + BSZ, 256>>>(idx, m1, m2, out);
}